// round 3
// baseline (speedup 1.0000x reference)
#include <cuda_runtime.h>
#include <math.h>

#define BSZ 32
#define LL 4096
#define HH 512
#define PP 384
#define VV 32
#define TOUT 16
#define NC 16
#define CHUNK 255          // (LL - TOUT) / NC
#define RR (BSZ*TOUT)      // 512 output rows
#define KXC (2*PP)         // 768

typedef unsigned long long u64;

// ---------------- scratch (device globals) ----------------
__device__ __align__(16) float2 d_Lbar[PP];
__device__ __align__(16) float2 d_Wpow[NC*PP];     // Lbar^(CHUNK*k)
__device__ __align__(16) float  d_BgRe[VV*PP];
__device__ __align__(16) float  d_BgIm[VV*PP];
__device__ __align__(16) float  d_xpartRe[BSZ*NC*PP];
__device__ __align__(16) float  d_xpartIm[BSZ*NC*PP];
__device__ __align__(16) float  d_Xbig[RR*KXC];    // [r][768] = [2xr | -2xi]
__device__ __align__(16) float  d_y[RR*HH];
__device__ __align__(16) float  d_h1[RR*HH];
__device__ __align__(16) float  d_W2t[VV*HH];      // W2 transposed [v][h]

// ---------------- packed f32x2 helpers ----------------
__device__ __forceinline__ u64 pk2(float lo, float hi) {
    u64 r; asm("mov.b64 %0, {%1, %2};" : "=l"(r) : "f"(lo), "f"(hi)); return r;
}
__device__ __forceinline__ float2 upk(u64 x) {
    float lo, hi; asm("mov.b64 {%0, %1}, %2;" : "=f"(lo), "=f"(hi) : "l"(x));
    return make_float2(lo, hi);
}
__device__ __forceinline__ u64 fma2(u64 a, u64 b, u64 c) {
    u64 d; asm("fma.rn.f32x2 %0, %1, %2, %3;" : "=l"(d) : "l"(a), "l"(b), "l"(c));
    return d;
}

// ================= K1: all preprocessing (400 blocks) =================
// blocks [0,384): per-mode constants + Bg rows
// blocks [384,400): transpose W2 -> W2t
__global__ void __launch_bounds__(256) prep_all(
    const float* __restrict__ Lre, const float* __restrict__ Lim,
    const float* __restrict__ logstep,
    const float* __restrict__ embed, const float* __restrict__ Bre,
    const float* __restrict__ Bim, const float* __restrict__ W2)
{
    int bid = blockIdx.x, tid = threadIdx.x;
    if (bid >= PP) {
        int i = bid - PP;
        for (int e = i*1024 + tid; e < (i+1)*1024; e += 256) {
            int h = e >> 5, v = e & 31;
            d_W2t[v*HH + h] = W2[e];
        }
        return;
    }
    int p = bid;
    __shared__ float sBr[HH], sBi[HH];
    __shared__ float2 sg;
    // stage B row
    for (int h = tid; h < HH; h += 256) {
        sBr[h] = Bre[p*HH + h];
        sBi[h] = Bim[p*HH + h];
    }
    // lanes 0..15 of warp 0: Lbar, g, Wpow[k]
    if (tid < NC) {
        float lre = Lre[p], lim = Lim[p];
        float step = (float)exp((double)logstep[p]);
        float zr = lre * step, zi = lim * step;
        double m = exp((double)zr);
        double sv, cv; sincos((double)zi, &sv, &cv);
        float br = (float)(m * cv), bi = (float)(m * sv);
        if (tid == 0) {
            d_Lbar[p] = make_float2(br, bi);
            float ar = br - 1.f, ai = bi;
            float den = lre*lre + lim*lim;
            sg = make_float2((ar*lre + ai*lim)/den, (ai*lre - ar*lim)/den);
        }
        // Wpow[k] = (fp32 Lbar)^(CHUNK*k), exact in double
        double dbr = (double)br, dbi = (double)bi;
        double lr = log(sqrt(dbr*dbr + dbi*dbi));
        double th = atan2(dbi, dbr);
        double e  = (double)(CHUNK * tid);
        double mm = exp(lr * e);
        double s2, c2; sincos(th * e, &s2, &c2);
        d_Wpow[tid*PP + p] = make_float2((float)(mm*c2), (float)(mm*s2));
    }
    __syncthreads();
    int warp = tid >> 5, lane = tid & 31;
    float2 g = sg;
    for (int v = warp; v < VV; v += 8) {
        float sr = 0.f, si = 0.f;
        for (int h = lane; h < HH; h += 32) {
            float e = embed[v*HH + h];
            sr = fmaf(e, sBr[h], sr);
            si = fmaf(e, sBi[h], si);
        }
        #pragma unroll
        for (int o = 16; o; o >>= 1) {
            sr += __shfl_xor_sync(0xffffffffu, sr, o);
            si += __shfl_xor_sync(0xffffffffu, si, o);
        }
        if (lane == 0) {
            d_BgRe[v*PP + p] = g.x*sr - g.y*si;
            d_BgIm[v*PP + p] = g.x*si + g.y*sr;
        }
    }
}

// ================= K2: chunked scan, SoA, 4 modes/thread =================
__global__ void __launch_bounds__(96) scan_chunks(const int* __restrict__ tokens) {
    __shared__ int stok[CHUNK];
    int b = blockIdx.y, c = blockIdx.x, t = threadIdx.x;
    for (int i = t; i < CHUNK; i += 96) stok[i] = tokens[b*LL + c*CHUNK + i];
    __syncthreads();
    int p0 = t * 4;
    float2 L0 = d_Lbar[p0+0], L1 = d_Lbar[p0+1];
    float2 L2 = d_Lbar[p0+2], L3 = d_Lbar[p0+3];
    u64 LrA = pk2(L0.x, L1.x), LrB = pk2(L2.x, L3.x);
    u64 LiA = pk2(L0.y, L1.y), LiB = pk2(L2.y, L3.y);
    u64 nLiA = pk2(-L0.y, -L1.y), nLiB = pk2(-L2.y, -L3.y);
    u64 XR0 = 0ull, XR1 = 0ull, XI0 = 0ull, XI1 = 0ull;
    const float* bgr = d_BgRe + p0;
    const float* bgi = d_BgIm + p0;
    #pragma unroll 5
    for (int i = 0; i < CHUNK; ++i) {
        int off = stok[i] * PP;
        ulonglong2 br = *(const ulonglong2*)(bgr + off);
        ulonglong2 bi = *(const ulonglong2*)(bgi + off);
        u64 nR0 = fma2(LrA, XR0, fma2(nLiA, XI0, br.x));
        u64 nI0 = fma2(LrA, XI0, fma2(LiA,  XR0, bi.x));
        u64 nR1 = fma2(LrB, XR1, fma2(nLiB, XI1, br.y));
        u64 nI1 = fma2(LrB, XI1, fma2(LiB,  XR1, bi.y));
        XR0 = nR0; XI0 = nI0; XR1 = nR1; XI1 = nI1;
    }
    int base = (b*NC + c)*PP + p0;
    *(ulonglong2*)(d_xpartRe + base) = make_ulonglong2(XR0, XR1);
    *(ulonglong2*)(d_xpartIm + base) = make_ulonglong2(XI0, XI1);
}

// ================= K3: combine chunks + 16 emission steps =================
__global__ void __launch_bounds__(192) combine_emit(const int* __restrict__ tokens) {
    int b = blockIdx.x;
    int p = blockIdx.y * 192 + threadIdx.x;
    float2 Lb = d_Lbar[p];
    float xr = 0.f, xi = 0.f;
    #pragma unroll
    for (int c = 0; c < NC; ++c) {
        float2 W = d_Wpow[(NC - 1 - c)*PP + p];
        int base = (b*NC + c)*PP + p;
        float pr = d_xpartRe[base], pi = d_xpartIm[base];
        xr = fmaf(W.x, pr, fmaf(-W.y, pi, xr));
        xi = fmaf(W.x, pi, fmaf( W.y, pr, xi));
    }
    int tk[TOUT];
    #pragma unroll
    for (int j = 0; j < TOUT; ++j) tk[j] = tokens[b*LL + (LL - TOUT) + j];
    #pragma unroll
    for (int j = 0; j < TOUT; ++j) {
        float bgr = d_BgRe[tk[j]*PP + p];
        float bgi = d_BgIm[tk[j]*PP + p];
        float nr = fmaf(Lb.x, xr, fmaf(-Lb.y, xi, bgr));
        float ni = fmaf(Lb.y, xr, fmaf( Lb.x, xi, bgi));
        xr = nr; xi = ni;
        int r = b*TOUT + j;
        d_Xbig[r*KXC + p]      =  2.f * xr;
        d_Xbig[r*KXC + PP + p] = -2.f * xi;
    }
}

// ================= GEMM cores: 32x64 tile, 128 threads, FFMA2 =================
#define SA_ROW 34   // u64 per smem A row (padded)
#define SB_ROW 68   // floats per smem B row (padded)

// K4: y = Xbig @ [Cre^T; Cim^T] + u*D   (B transposed on the fly)
__global__ void __launch_bounds__(128) gemm_xc(
    const int* __restrict__ tokens, const float* __restrict__ embed,
    const float* __restrict__ D,
    const float* __restrict__ Cre, const float* __restrict__ Cim)
{
    __shared__ u64   sA[16*SA_ROW];
    __shared__ float sB[16*SB_ROW];
    int tid = threadIdx.x;
    int tm = tid >> 3, tn = tid & 7;
    int row0 = blockIdx.y * 32, col0 = blockIdx.x * 64;
    u64 acc[2][4] = {};
    int ar = tid >> 2, as = tid & 3;
    for (int kk = 0; kk < KXC; kk += 16) {
        float4 av = *(const float4*)(d_Xbig + (size_t)(row0 + ar)*KXC + kk + 4*as);
        sA[(4*as+0)*SA_ROW + ar] = pk2(av.x, av.x);
        sA[(4*as+1)*SA_ROW + ar] = pk2(av.y, av.y);
        sA[(4*as+2)*SA_ROW + ar] = pk2(av.z, av.z);
        sA[(4*as+3)*SA_ROW + ar] = pk2(av.w, av.w);
        const float* Bsrc = (kk < PP) ? Cre : Cim;
        int koff = (kk < PP) ? kk : kk - PP;
        #pragma unroll
        for (int it = 0; it < 2; ++it) {
            int idx = tid + it*128;
            int hr = idx & 63, s2 = idx >> 6;
            float4 bv = *(const float4*)(Bsrc + (size_t)(col0 + hr)*PP + koff + 4*s2);
            sB[(4*s2+0)*SB_ROW + hr] = bv.x;
            sB[(4*s2+1)*SB_ROW + hr] = bv.y;
            sB[(4*s2+2)*SB_ROW + hr] = bv.z;
            sB[(4*s2+3)*SB_ROW + hr] = bv.w;
        }
        __syncthreads();
        #pragma unroll
        for (int k = 0; k < 16; ++k) {
            ulonglong2 aa = *(const ulonglong2*)(sA + k*SA_ROW + tm*2);
            const u64* bp = (const u64*)(sB + k*SB_ROW);
            ulonglong2 b0 = *(const ulonglong2*)(bp + tn*4);
            ulonglong2 b1 = *(const ulonglong2*)(bp + tn*4 + 2);
            acc[0][0]=fma2(aa.x,b0.x,acc[0][0]); acc[0][1]=fma2(aa.x,b0.y,acc[0][1]);
            acc[0][2]=fma2(aa.x,b1.x,acc[0][2]); acc[0][3]=fma2(aa.x,b1.y,acc[0][3]);
            acc[1][0]=fma2(aa.y,b0.x,acc[1][0]); acc[1][1]=fma2(aa.y,b0.y,acc[1][1]);
            acc[1][2]=fma2(aa.y,b1.x,acc[1][2]); acc[1][3]=fma2(aa.y,b1.y,acc[1][3]);
        }
        __syncthreads();
    }
    #pragma unroll
    for (int i = 0; i < 2; ++i) {
        int r = row0 + tm*2 + i;
        int tok = tokens[(r >> 4)*LL + (LL - TOUT) + (r & 15)];
        const float* urow = embed + (size_t)tok*HH;
        int hb = col0 + tn*8;
        #pragma unroll
        for (int j = 0; j < 4; ++j) {
            float2 f = upk(acc[i][j]);
            int h = hb + 2*j;
            d_y[(size_t)r*HH + h]     = f.x + urow[h]   * D[h];
            d_y[(size_t)r*HH + h + 1] = f.y + urow[h+1] * D[h+1];
        }
    }
}

// K5: h1 = relu(y @ W1 + b1)
__global__ void __launch_bounds__(128) gemm_yw(
    const float* __restrict__ W1, const float* __restrict__ b1)
{
    __shared__ u64   sA[16*SA_ROW];
    __shared__ float sB[16*SB_ROW];
    int tid = threadIdx.x;
    int tm = tid >> 3, tn = tid & 7;
    int row0 = blockIdx.y * 32, col0 = blockIdx.x * 64;
    u64 acc[2][4] = {};
    int ar = tid >> 2, as = tid & 3;
    for (int kk = 0; kk < HH; kk += 16) {
        float4 av = *(const float4*)(d_y + (size_t)(row0 + ar)*HH + kk + 4*as);
        sA[(4*as+0)*SA_ROW + ar] = pk2(av.x, av.x);
        sA[(4*as+1)*SA_ROW + ar] = pk2(av.y, av.y);
        sA[(4*as+2)*SA_ROW + ar] = pk2(av.z, av.z);
        sA[(4*as+3)*SA_ROW + ar] = pk2(av.w, av.w);
        #pragma unroll
        for (int it = 0; it < 2; ++it) {
            int idx = tid + it*128;
            int bk = idx >> 4, bc = (idx & 15)*4;
            *(float4*)(sB + bk*SB_ROW + bc) =
                *(const float4*)(W1 + (size_t)(kk + bk)*HH + col0 + bc);
        }
        __syncthreads();
        #pragma unroll
        for (int k = 0; k < 16; ++k) {
            ulonglong2 aa = *(const ulonglong2*)(sA + k*SA_ROW + tm*2);
            const u64* bp = (const u64*)(sB + k*SB_ROW);
            ulonglong2 b0 = *(const ulonglong2*)(bp + tn*4);
            ulonglong2 b1v = *(const ulonglong2*)(bp + tn*4 + 2);
            acc[0][0]=fma2(aa.x,b0.x,acc[0][0]); acc[0][1]=fma2(aa.x,b0.y,acc[0][1]);
            acc[0][2]=fma2(aa.x,b1v.x,acc[0][2]); acc[0][3]=fma2(aa.x,b1v.y,acc[0][3]);
            acc[1][0]=fma2(aa.y,b0.x,acc[1][0]); acc[1][1]=fma2(aa.y,b0.y,acc[1][1]);
            acc[1][2]=fma2(aa.y,b1v.x,acc[1][2]); acc[1][3]=fma2(aa.y,b1v.y,acc[1][3]);
        }
        __syncthreads();
    }
    #pragma unroll
    for (int i = 0; i < 2; ++i) {
        int r = row0 + tm*2 + i;
        int hb = col0 + tn*8;
        #pragma unroll
        for (int j = 0; j < 4; ++j) {
            float2 f = upk(acc[i][j]);
            int h = hb + 2*j;
            d_h1[(size_t)r*HH + h]     = fmaxf(f.x + b1[h],   0.f);
            d_h1[(size_t)r*HH + h + 1] = fmaxf(f.y + b1[h+1], 0.f);
        }
    }
}

// ================= K6: out = h1 @ W2 + b2 (uses W2t) =================
__global__ void __launch_bounds__(256) final_out(const float* __restrict__ b2,
                                                 float* __restrict__ out) {
    int idx = blockIdx.x*256 + threadIdx.x;      // RR*VV = 16384
    int r = idx >> 5, v = idx & 31;
    const float* hrow = d_h1 + (size_t)r*HH;
    const float* wrow = d_W2t + (size_t)v*HH;
    u64 a = 0ull, b = 0ull;
    #pragma unroll 8
    for (int h = 0; h < HH; h += 4) {
        ulonglong2 hv = *(const ulonglong2*)(hrow + h);
        ulonglong2 wv = *(const ulonglong2*)(wrow + h);
        a = fma2(hv.x, wv.x, a);
        b = fma2(hv.y, wv.y, b);
    }
    float2 fa = upk(a), fb = upk(b);
    out[idx] = fa.x + fa.y + fb.x + fb.y + b2[v];
}

// ================= launcher =================
extern "C" void kernel_launch(void* const* d_in, const int* in_sizes, int n_in,
                              void* d_out, int out_size) {
    const int*   tokens  = (const int*)  d_in[0];
    const float* embed   = (const float*)d_in[1];
    const float* Lre     = (const float*)d_in[2];
    const float* Lim     = (const float*)d_in[3];
    const float* Bre     = (const float*)d_in[4];
    const float* Bim     = (const float*)d_in[5];
    const float* Cre     = (const float*)d_in[6];
    const float* Cim     = (const float*)d_in[7];
    const float* D       = (const float*)d_in[8];
    const float* logstep = (const float*)d_in[9];
    const float* W1      = (const float*)d_in[10];
    const float* b1      = (const float*)d_in[11];
    const float* W2      = (const float*)d_in[12];
    const float* b2      = (const float*)d_in[13];
    float* out = (float*)d_out;

    prep_all<<<PP + 16, 256>>>(Lre, Lim, logstep, embed, Bre, Bim, W2);
    scan_chunks<<<dim3(NC, BSZ), 96>>>(tokens);
    combine_emit<<<dim3(BSZ, 2), 192>>>(tokens);
    gemm_xc<<<dim3(8, 16), 128>>>(tokens, embed, D, Cre, Cim);
    gemm_yw<<<dim3(8, 16), 128>>>(W1, b1);
    final_out<<<64, 256>>>(b2, out);
}

// round 5
// speedup vs baseline: 1.4995x; 1.4995x over previous
#include <cuda_runtime.h>
#include <math.h>

#define BSZ 32
#define LL 4096
#define HH 512
#define PP 384
#define VV 32
#define TOUT 16
#define NC 16
#define CHUNK 255          // (LL - TOUT) / NC
#define RR (BSZ*TOUT)      // 512 output rows
#define KXC (2*PP)         // 768
#define SK 4               // split-K factor

typedef unsigned long long u64;

// ---------------- scratch (device globals) ----------------
__device__ __align__(16) float2 d_Lbar[PP];
__device__ __align__(16) float2 d_Wpow[NC*PP];
__device__ __align__(16) float  d_BgRe[VV*PP];
__device__ __align__(16) float  d_BgIm[VV*PP];
__device__ __align__(16) float  d_xpartRe[BSZ*NC*PP];
__device__ __align__(16) float  d_xpartIm[BSZ*NC*PP];
__device__ __align__(16) float  d_Xbig[RR*KXC];     // [r][768] = [2xr | -2xi]
__device__ __align__(16) float  d_Cbig[KXC*HH];     // [768][512] = [Cre^T ; Cim^T]
__device__ __align__(16) float  d_y[RR*HH];
__device__ __align__(16) float  d_h1[RR*HH];
__device__ __align__(16) float  d_W2t[VV*HH];
__device__ __align__(16) float  d_part[SK*RR*HH];   // split-K partials

// ---------------- packed f32x2 helpers ----------------
__device__ __forceinline__ u64 pk2(float lo, float hi) {
    u64 r; asm("mov.b64 %0, {%1, %2};" : "=l"(r) : "f"(lo), "f"(hi)); return r;
}
__device__ __forceinline__ float2 upk(u64 x) {
    float lo, hi; asm("mov.b64 {%0, %1}, %2;" : "=f"(lo), "=f"(hi) : "l"(x));
    return make_float2(lo, hi);
}
__device__ __forceinline__ u64 fma2(u64 a, u64 b, u64 c) {
    u64 d; asm("fma.rn.f32x2 %0, %1, %2, %3;" : "=l"(d) : "l"(a), "l"(b), "l"(c));
    return d;
}

// ================= K1: all preprocessing =================
__global__ void __launch_bounds__(256) prep_all(
    const float* __restrict__ Lre, const float* __restrict__ Lim,
    const float* __restrict__ logstep,
    const float* __restrict__ embed, const float* __restrict__ Bre,
    const float* __restrict__ Bim, const float* __restrict__ W2,
    const float* __restrict__ Cre, const float* __restrict__ Cim)
{
    int bid = blockIdx.x, tid = threadIdx.x;
    if (bid >= PP + 16) {                       // build Cbig[k][h]
        int k = bid - (PP + 16);                // 0..767
        const float* src = (k < PP) ? Cre : Cim;
        int kk = (k < PP) ? k : k - PP;
        for (int h = tid; h < HH; h += 256)
            d_Cbig[k*HH + h] = src[(size_t)h*PP + kk];
        return;
    }
    if (bid >= PP) {                            // transpose W2
        int i = bid - PP;
        for (int e = i*1024 + tid; e < (i+1)*1024; e += 256) {
            int h = e >> 5, v = e & 31;
            d_W2t[v*HH + h] = W2[e];
        }
        return;
    }
    int p = bid;
    __shared__ float sBr[HH], sBi[HH];
    __shared__ float2 sg;
    for (int h = tid; h < HH; h += 256) {
        sBr[h] = Bre[p*HH + h];
        sBi[h] = Bim[p*HH + h];
    }
    if (tid < NC) {
        float lre = Lre[p], lim = Lim[p];
        float step = (float)exp((double)logstep[p]);
        float zr = lre * step, zi = lim * step;
        double m = exp((double)zr);
        double sv, cv; sincos((double)zi, &sv, &cv);
        float br = (float)(m * cv), bi = (float)(m * sv);
        if (tid == 0) {
            d_Lbar[p] = make_float2(br, bi);
            float ar = br - 1.f, ai = bi;
            float den = lre*lre + lim*lim;
            sg = make_float2((ar*lre + ai*lim)/den, (ai*lre - ar*lim)/den);
        }
        double dbr = (double)br, dbi = (double)bi;
        double lr = log(sqrt(dbr*dbr + dbi*dbi));
        double th = atan2(dbi, dbr);
        double e  = (double)(CHUNK * tid);
        double mm = exp(lr * e);
        double s2, c2; sincos(th * e, &s2, &c2);
        d_Wpow[tid*PP + p] = make_float2((float)(mm*c2), (float)(mm*s2));
    }
    __syncthreads();
    int warp = tid >> 5, lane = tid & 31;
    float2 g = sg;
    for (int v = warp; v < VV; v += 8) {
        float sr = 0.f, si = 0.f;
        for (int h = lane; h < HH; h += 32) {
            float e = embed[v*HH + h];
            sr = fmaf(e, sBr[h], sr);
            si = fmaf(e, sBi[h], si);
        }
        #pragma unroll
        for (int o = 16; o; o >>= 1) {
            sr += __shfl_xor_sync(0xffffffffu, sr, o);
            si += __shfl_xor_sync(0xffffffffu, si, o);
        }
        if (lane == 0) {
            d_BgRe[v*PP + p] = g.x*sr - g.y*si;
            d_BgIm[v*PP + p] = g.x*si + g.y*sr;
        }
    }
}

// ================= K2: chunked scan, SoA, 4 modes/thread =================
__global__ void __launch_bounds__(96) scan_chunks(const int* __restrict__ tokens) {
    __shared__ int stok[CHUNK];
    int b = blockIdx.y, c = blockIdx.x, t = threadIdx.x;
    for (int i = t; i < CHUNK; i += 96) stok[i] = tokens[b*LL + c*CHUNK + i];
    __syncthreads();
    int p0 = t * 4;
    float2 L0 = d_Lbar[p0+0], L1 = d_Lbar[p0+1];
    float2 L2 = d_Lbar[p0+2], L3 = d_Lbar[p0+3];
    u64 LrA = pk2(L0.x, L1.x), LrB = pk2(L2.x, L3.x);
    u64 LiA = pk2(L0.y, L1.y), LiB = pk2(L2.y, L3.y);
    u64 nLiA = pk2(-L0.y, -L1.y), nLiB = pk2(-L2.y, -L3.y);
    u64 XR0 = 0ull, XR1 = 0ull, XI0 = 0ull, XI1 = 0ull;
    const float* bgr = d_BgRe + p0;
    const float* bgi = d_BgIm + p0;
    #pragma unroll 5
    for (int i = 0; i < CHUNK; ++i) {
        int off = stok[i] * PP;
        ulonglong2 br = *(const ulonglong2*)(bgr + off);
        ulonglong2 bi = *(const ulonglong2*)(bgi + off);
        u64 nR0 = fma2(LrA, XR0, fma2(nLiA, XI0, br.x));
        u64 nI0 = fma2(LrA, XI0, fma2(LiA,  XR0, bi.x));
        u64 nR1 = fma2(LrB, XR1, fma2(nLiB, XI1, br.y));
        u64 nI1 = fma2(LrB, XI1, fma2(LiB,  XR1, bi.y));
        XR0 = nR0; XI0 = nI0; XR1 = nR1; XI1 = nI1;
    }
    int base = (b*NC + c)*PP + p0;
    *(ulonglong2*)(d_xpartRe + base) = make_ulonglong2(XR0, XR1);
    *(ulonglong2*)(d_xpartIm + base) = make_ulonglong2(XI0, XI1);
}

// ================= K3: combine chunks + 16 emission steps =================
__global__ void __launch_bounds__(192) combine_emit(const int* __restrict__ tokens) {
    int b = blockIdx.x;
    int p = blockIdx.y * 192 + threadIdx.x;
    float2 Lb = d_Lbar[p];
    float xr = 0.f, xi = 0.f;
    #pragma unroll
    for (int c = 0; c < NC; ++c) {
        float2 W = d_Wpow[(NC - 1 - c)*PP + p];
        int base = (b*NC + c)*PP + p;
        float pr = d_xpartRe[base], pi = d_xpartIm[base];
        xr = fmaf(W.x, pr, fmaf(-W.y, pi, xr));
        xi = fmaf(W.x, pi, fmaf( W.y, pr, xi));
    }
    int tk[TOUT];
    #pragma unroll
    for (int j = 0; j < TOUT; ++j) tk[j] = tokens[b*LL + (LL - TOUT) + j];
    #pragma unroll
    for (int j = 0; j < TOUT; ++j) {
        float bgr = d_BgRe[tk[j]*PP + p];
        float bgi = d_BgIm[tk[j]*PP + p];
        float nr = fmaf(Lb.x, xr, fmaf(-Lb.y, xi, bgr));
        float ni = fmaf(Lb.y, xr, fmaf( Lb.x, xi, bgi));
        xr = nr; xi = ni;
        int r = b*TOUT + j;
        d_Xbig[r*KXC + p]      =  2.f * xr;
        d_Xbig[r*KXC + PP + p] = -2.f * xi;
    }
}

// ================= split-K GEMM: 64x128 tile, 128 thr, 8x8/thread =================
__global__ void __launch_bounds__(128) gemm_sk(const float* __restrict__ A,
                                               const float* __restrict__ B,
                                               int Ktot) {
    __shared__ __align__(16) u64   sA[16][66];    // 64 A-rows (dup-packed), padded
    __shared__ __align__(16) float sB[16][132];   // 128 B-cols, padded
    int tid = threadIdx.x;
    int tx = tid & 15;          // col group: cols tx*8 .. tx*8+7
    int ty = tid >> 4;          // row group: rows ty*8 .. ty*8+7  (ty in [0,8))
    int row0 = blockIdx.y * 64, col0 = blockIdx.x * 128;
    int Kc = Ktot / SK;
    int k0 = blockIdx.z * Kc;
    u64 acc[8][4];
    #pragma unroll
    for (int i = 0; i < 8; ++i)
        #pragma unroll
        for (int j = 0; j < 4; ++j) acc[i][j] = 0ull;

    for (int kk = 0; kk < Kc; kk += 16) {
        #pragma unroll
        for (int it = 0; it < 2; ++it) {          // A: 64 rows x 16 k
            int idx = tid + it*128;               // 0..255
            int row = idx & 63, kq = idx >> 6;    // kq in [0,4)
            float4 v = *(const float4*)(A + (size_t)(row0+row)*Ktot + k0 + kk + kq*4);
            sA[kq*4+0][row] = pk2(v.x, v.x);
            sA[kq*4+1][row] = pk2(v.y, v.y);
            sA[kq*4+2][row] = pk2(v.z, v.z);
            sA[kq*4+3][row] = pk2(v.w, v.w);
        }
        #pragma unroll
        for (int it = 0; it < 4; ++it) {          // B: 16 k x 128 cols
            int idx = tid + it*128;               // 0..511
            int kr = idx >> 5, cb = (idx & 31) * 4;
            *(float4*)&sB[kr][cb] =
                *(const float4*)(B + (size_t)(k0 + kk + kr)*HH + col0 + cb);
        }
        __syncthreads();
        #pragma unroll
        for (int k = 0; k < 16; ++k) {
            u64 a[8], bb[4];
            *(ulonglong2*)&a[0] = *(const ulonglong2*)&sA[k][ty*8+0];
            *(ulonglong2*)&a[2] = *(const ulonglong2*)&sA[k][ty*8+2];
            *(ulonglong2*)&a[4] = *(const ulonglong2*)&sA[k][ty*8+4];
            *(ulonglong2*)&a[6] = *(const ulonglong2*)&sA[k][ty*8+6];
            const float* bp = &sB[k][tx*8];
            *(ulonglong2*)&bb[0] = *(const ulonglong2*)(bp);
            *(ulonglong2*)&bb[2] = *(const ulonglong2*)(bp + 4);
            #pragma unroll
            for (int i = 0; i < 8; ++i)
                #pragma unroll
                for (int j = 0; j < 4; ++j)
                    acc[i][j] = fma2(a[i], bb[j], acc[i][j]);
        }
        __syncthreads();
    }
    float* out = d_part + (size_t)blockIdx.z * (RR*HH);
    #pragma unroll
    for (int i = 0; i < 8; ++i) {
        float* orow = out + (size_t)(row0 + ty*8 + i)*HH + col0 + tx*8;
        float2 f0 = upk(acc[i][0]), f1 = upk(acc[i][1]);
        float2 f2 = upk(acc[i][2]), f3 = upk(acc[i][3]);
        *(float4*)(orow)     = make_float4(f0.x, f0.y, f1.x, f1.y);
        *(float4*)(orow + 4) = make_float4(f2.x, f2.y, f3.x, f3.y);
    }
}

// ================= reduces (vectorized, fused epilogues) =================
__global__ void __launch_bounds__(256) reduce_y(const int* __restrict__ tokens,
                                                const float* __restrict__ embed,
                                                const float* __restrict__ D) {
    int idx = blockIdx.x*256 + threadIdx.x;      // RR*HH/4 items
    int i4 = idx * 4;
    int r = i4 >> 9, h = i4 & 511;
    int tok = tokens[(r >> 4)*LL + (LL - TOUT) + (r & 15)];
    float4 u  = *(const float4*)(embed + (size_t)tok*HH + h);
    float4 dv = *(const float4*)(D + h);
    float4 s = make_float4(u.x*dv.x, u.y*dv.y, u.z*dv.z, u.w*dv.w);
    #pragma unroll
    for (int z = 0; z < SK; ++z) {
        float4 p = *(const float4*)(d_part + (size_t)z*RR*HH + i4);
        s.x += p.x; s.y += p.y; s.z += p.z; s.w += p.w;
    }
    *(float4*)(d_y + i4) = s;
}
__global__ void __launch_bounds__(256) reduce_h1(const float* __restrict__ b1) {
    int idx = blockIdx.x*256 + threadIdx.x;
    int i4 = idx * 4;
    int h = i4 & 511;
    float4 s = *(const float4*)(b1 + h);
    #pragma unroll
    for (int z = 0; z < SK; ++z) {
        float4 p = *(const float4*)(d_part + (size_t)z*RR*HH + i4);
        s.x += p.x; s.y += p.y; s.z += p.z; s.w += p.w;
    }
    s.x = fmaxf(s.x, 0.f); s.y = fmaxf(s.y, 0.f);
    s.z = fmaxf(s.z, 0.f); s.w = fmaxf(s.w, 0.f);
    *(float4*)(d_h1 + i4) = s;
}

// ================= final: out = h1 @ W2 + b2 (W2t) =================
__global__ void __launch_bounds__(256) final_out(const float* __restrict__ b2,
                                                 float* __restrict__ out) {
    int idx = blockIdx.x*256 + threadIdx.x;      // RR*VV
    int r = idx >> 5, v = idx & 31;
    const float* hrow = d_h1 + (size_t)r*HH;
    const float* wrow = d_W2t + (size_t)v*HH;
    u64 a = 0ull, b = 0ull;
    #pragma unroll 8
    for (int h = 0; h < HH; h += 4) {
        ulonglong2 hv = *(const ulonglong2*)(hrow + h);
        ulonglong2 wv = *(const ulonglong2*)(wrow + h);
        a = fma2(hv.x, wv.x, a);
        b = fma2(hv.y, wv.y, b);
    }
    float2 fa = upk(a), fb = upk(b);
    out[idx] = fa.x + fa.y + fb.x + fb.y + b2[v];
}

// ================= launcher =================
extern "C" void kernel_launch(void* const* d_in, const int* in_sizes, int n_in,
                              void* d_out, int out_size) {
    const int*   tokens  = (const int*)  d_in[0];
    const float* embed   = (const float*)d_in[1];
    const float* Lre     = (const float*)d_in[2];
    const float* Lim     = (const float*)d_in[3];
    const float* Bre     = (const float*)d_in[4];
    const float* Bim     = (const float*)d_in[5];
    const float* Cre     = (const float*)d_in[6];
    const float* Cim     = (const float*)d_in[7];
    const float* D       = (const float*)d_in[8];
    const float* logstep = (const float*)d_in[9];
    const float* W1      = (const float*)d_in[10];
    const float* b1      = (const float*)d_in[11];
    const float* W2      = (const float*)d_in[12];
    const float* b2      = (const float*)d_in[13];
    float* out = (float*)d_out;

    float *xbig_p, *cbig_p, *y_p;
    cudaGetSymbolAddress((void**)&xbig_p, d_Xbig);
    cudaGetSymbolAddress((void**)&cbig_p, d_Cbig);
    cudaGetSymbolAddress((void**)&y_p,    d_y);

    prep_all<<<PP + 16 + KXC, 256>>>(Lre, Lim, logstep, embed, Bre, Bim, W2, Cre, Cim);
    scan_chunks<<<dim3(NC, BSZ), 96>>>(tokens);
    combine_emit<<<dim3(BSZ, 2), 192>>>(tokens);
    gemm_sk<<<dim3(4, 8, SK), 128>>>(xbig_p, cbig_p, KXC);   // y partials
    reduce_y<<<(RR*HH/4)/256, 256>>>(tokens, embed, D);
    gemm_sk<<<dim3(4, 8, SK), 128>>>(y_p, W1, HH);           // h1 partials
    reduce_h1<<<(RR*HH/4)/256, 256>>>(b1);
    final_out<<<(RR*VV)/256, 256>>>(b2, out);
}

// round 6
// speedup vs baseline: 1.5765x; 1.0513x over previous
#include <cuda_runtime.h>
#include <math.h>

#define BSZ 32
#define LL 4096
#define HH 512
#define PP 384
#define VV 32
#define TOUT 16
#define NC 16
#define CHUNK 255          // (LL - TOUT) / NC
#define RR (BSZ*TOUT)      // 512 output rows
#define KXC (2*PP)         // 768
#define SK 8               // split-K factor

typedef unsigned long long u64;

// ---------------- scratch (device globals) ----------------
__device__ __align__(16) float2 d_Lbar[PP];
__device__ __align__(16) float2 d_Wpow[NC*PP];
__device__ __align__(16) float  d_BgRe[VV*PP];
__device__ __align__(16) float  d_BgIm[VV*PP];
__device__ __align__(16) float  d_xpartRe[BSZ*NC*PP];
__device__ __align__(16) float  d_xpartIm[BSZ*NC*PP];
__device__ __align__(16) float  d_Xbig[RR*KXC];     // [r][768] = [2xr | -2xi]
__device__ __align__(16) float  d_Cbig[KXC*HH];     // [768][512] = [Cre^T ; Cim^T]
__device__ __align__(16) float  d_y[RR*HH];
__device__ __align__(16) float  d_h1[RR*HH];
__device__ __align__(16) float  d_W2t[VV*HH];
__device__ __align__(16) float  d_part[SK*RR*HH];   // split-K partials (8 MB)

// ---------------- packed f32x2 helpers ----------------
__device__ __forceinline__ u64 pk2(float lo, float hi) {
    u64 r; asm("mov.b64 %0, {%1, %2};" : "=l"(r) : "f"(lo), "f"(hi)); return r;
}
__device__ __forceinline__ float2 upk(u64 x) {
    float lo, hi; asm("mov.b64 {%0, %1}, %2;" : "=f"(lo), "=f"(hi) : "l"(x));
    return make_float2(lo, hi);
}
__device__ __forceinline__ u64 fma2(u64 a, u64 b, u64 c) {
    u64 d; asm("fma.rn.f32x2 %0, %1, %2, %3;" : "=l"(d) : "l"(a), "l"(b), "l"(c));
    return d;
}

// ================= K1: all preprocessing =================
__global__ void __launch_bounds__(256) prep_all(
    const float* __restrict__ Lre, const float* __restrict__ Lim,
    const float* __restrict__ logstep,
    const float* __restrict__ embed, const float* __restrict__ Bre,
    const float* __restrict__ Bim, const float* __restrict__ W2,
    const float* __restrict__ Cre, const float* __restrict__ Cim)
{
    int bid = blockIdx.x, tid = threadIdx.x;
    if (bid >= PP + 16) {                       // build Cbig[k][h]
        int k = bid - (PP + 16);                // 0..767
        const float* src = (k < PP) ? Cre : Cim;
        int kk = (k < PP) ? k : k - PP;
        for (int h = tid; h < HH; h += 256)
            d_Cbig[k*HH + h] = src[(size_t)h*PP + kk];
        return;
    }
    if (bid >= PP) {                            // transpose W2
        int i = bid - PP;
        for (int e = i*1024 + tid; e < (i+1)*1024; e += 256) {
            int h = e >> 5, v = e & 31;
            d_W2t[v*HH + h] = W2[e];
        }
        return;
    }
    int p = bid;
    __shared__ float sBr[HH], sBi[HH];
    __shared__ float2 sg;
    for (int h = tid; h < HH; h += 256) {
        sBr[h] = Bre[p*HH + h];
        sBi[h] = Bim[p*HH + h];
    }
    if (tid < NC) {
        float lre = Lre[p], lim = Lim[p];
        float step = (float)exp((double)logstep[p]);
        float zr = lre * step, zi = lim * step;
        double m = exp((double)zr);
        double sv, cv; sincos((double)zi, &sv, &cv);
        float br = (float)(m * cv), bi = (float)(m * sv);
        if (tid == 0) {
            d_Lbar[p] = make_float2(br, bi);
            float ar = br - 1.f, ai = bi;
            float den = lre*lre + lim*lim;
            sg = make_float2((ar*lre + ai*lim)/den, (ai*lre - ar*lim)/den);
        }
        double dbr = (double)br, dbi = (double)bi;
        double lr = log(sqrt(dbr*dbr + dbi*dbi));
        double th = atan2(dbi, dbr);
        double e  = (double)(CHUNK * tid);
        double mm = exp(lr * e);
        double s2, c2; sincos(th * e, &s2, &c2);
        d_Wpow[tid*PP + p] = make_float2((float)(mm*c2), (float)(mm*s2));
    }
    __syncthreads();
    int warp = tid >> 5, lane = tid & 31;
    float2 g = sg;
    for (int v = warp; v < VV; v += 8) {
        float sr = 0.f, si = 0.f;
        for (int h = lane; h < HH; h += 32) {
            float e = embed[v*HH + h];
            sr = fmaf(e, sBr[h], sr);
            si = fmaf(e, sBi[h], si);
        }
        #pragma unroll
        for (int o = 16; o; o >>= 1) {
            sr += __shfl_xor_sync(0xffffffffu, sr, o);
            si += __shfl_xor_sync(0xffffffffu, si, o);
        }
        if (lane == 0) {
            d_BgRe[v*PP + p] = g.x*sr - g.y*si;
            d_BgIm[v*PP + p] = g.x*si + g.y*sr;
        }
    }
}

// ================= K2: chunked scan, SoA, 4 modes/thread =================
__global__ void __launch_bounds__(96) scan_chunks(const int* __restrict__ tokens) {
    __shared__ int stok[CHUNK];
    int b = blockIdx.y, c = blockIdx.x, t = threadIdx.x;
    for (int i = t; i < CHUNK; i += 96) stok[i] = tokens[b*LL + c*CHUNK + i];
    __syncthreads();
    int p0 = t * 4;
    float2 L0 = d_Lbar[p0+0], L1 = d_Lbar[p0+1];
    float2 L2 = d_Lbar[p0+2], L3 = d_Lbar[p0+3];
    u64 LrA = pk2(L0.x, L1.x), LrB = pk2(L2.x, L3.x);
    u64 LiA = pk2(L0.y, L1.y), LiB = pk2(L2.y, L3.y);
    u64 nLiA = pk2(-L0.y, -L1.y), nLiB = pk2(-L2.y, -L3.y);
    u64 XR0 = 0ull, XR1 = 0ull, XI0 = 0ull, XI1 = 0ull;
    const float* bgr = d_BgRe + p0;
    const float* bgi = d_BgIm + p0;
    #pragma unroll 5
    for (int i = 0; i < CHUNK; ++i) {
        int off = stok[i] * PP;
        ulonglong2 br = *(const ulonglong2*)(bgr + off);
        ulonglong2 bi = *(const ulonglong2*)(bgi + off);
        u64 nR0 = fma2(LrA, XR0, fma2(nLiA, XI0, br.x));
        u64 nI0 = fma2(LrA, XI0, fma2(LiA,  XR0, bi.x));
        u64 nR1 = fma2(LrB, XR1, fma2(nLiB, XI1, br.y));
        u64 nI1 = fma2(LrB, XI1, fma2(LiB,  XR1, bi.y));
        XR0 = nR0; XI0 = nI0; XR1 = nR1; XI1 = nI1;
    }
    int base = (b*NC + c)*PP + p0;
    *(ulonglong2*)(d_xpartRe + base) = make_ulonglong2(XR0, XR1);
    *(ulonglong2*)(d_xpartIm + base) = make_ulonglong2(XI0, XI1);
}

// ================= K3: combine chunks + 16 emission steps =================
__global__ void __launch_bounds__(192) combine_emit(const int* __restrict__ tokens) {
    int b = blockIdx.x;
    int p = blockIdx.y * 192 + threadIdx.x;
    float2 Lb = d_Lbar[p];
    float xr = 0.f, xi = 0.f;
    #pragma unroll
    for (int c = 0; c < NC; ++c) {
        float2 W = d_Wpow[(NC - 1 - c)*PP + p];
        int base = (b*NC + c)*PP + p;
        float pr = d_xpartRe[base], pi = d_xpartIm[base];
        xr = fmaf(W.x, pr, fmaf(-W.y, pi, xr));
        xi = fmaf(W.x, pi, fmaf( W.y, pr, xi));
    }
    int tk[TOUT];
    #pragma unroll
    for (int j = 0; j < TOUT; ++j) tk[j] = tokens[b*LL + (LL - TOUT) + j];
    #pragma unroll
    for (int j = 0; j < TOUT; ++j) {
        float bgr = d_BgRe[tk[j]*PP + p];
        float bgi = d_BgIm[tk[j]*PP + p];
        float nr = fmaf(Lb.x, xr, fmaf(-Lb.y, xi, bgr));
        float ni = fmaf(Lb.y, xr, fmaf( Lb.x, xi, bgi));
        xr = nr; xi = ni;
        int r = b*TOUT + j;
        d_Xbig[r*KXC + p]      =  2.f * xr;
        d_Xbig[r*KXC + PP + p] = -2.f * xi;
    }
}

// ======= split-K GEMM: 64x128 tile, 256 thr, 4x8/thread, conflict-free =======
__global__ void __launch_bounds__(256) gemm_sk(const float* __restrict__ A,
                                               const float* __restrict__ B,
                                               int Ktot) {
    __shared__ __align__(16) u64   sA[16][66];    // 64 A-rows dup-packed, padded
    __shared__ __align__(16) float sB[16][132];   // 128 B-cols, padded
    int tid = threadIdx.x;
    int tx = tid & 15;          // col group: cols {tx*4..+3} and {64+tx*4..+3}
    int ty = tid >> 4;          // row group: rows ty*4 .. ty*4+3   (ty in [0,16))
    int row0 = blockIdx.y * 64, col0 = blockIdx.x * 128;
    int Kc = Ktot / SK;
    int k0 = blockIdx.z * Kc;
    u64 acc[4][4];
    #pragma unroll
    for (int i = 0; i < 4; ++i)
        #pragma unroll
        for (int j = 0; j < 4; ++j) acc[i][j] = 0ull;

    int arow = tid & 63, akq = tid >> 6;          // A staging: 256 thr cover 64x16
    for (int kk = 0; kk < Kc; kk += 16) {
        float4 v = *(const float4*)(A + (size_t)(row0 + arow)*Ktot + k0 + kk + akq*4);
        sA[akq*4+0][arow] = pk2(v.x, v.x);
        sA[akq*4+1][arow] = pk2(v.y, v.y);
        sA[akq*4+2][arow] = pk2(v.z, v.z);
        sA[akq*4+3][arow] = pk2(v.w, v.w);
        #pragma unroll
        for (int it = 0; it < 2; ++it) {          // B: 16k x 128 cols
            int idx = tid + it*256;               // 0..511
            int kr = idx >> 5, cb = (idx & 31) * 4;
            *(float4*)&sB[kr][cb] =
                *(const float4*)(B + (size_t)(k0 + kk + kr)*HH + col0 + cb);
        }
        __syncthreads();
        #pragma unroll
        for (int k = 0; k < 16; ++k) {
            u64 a[4], bb[4];
            *(ulonglong2*)&a[0]  = *(const ulonglong2*)&sA[k][ty*4];
            *(ulonglong2*)&a[2]  = *(const ulonglong2*)&sA[k][ty*4+2];
            *(ulonglong2*)&bb[0] = *(const ulonglong2*)&sB[k][tx*4];
            *(ulonglong2*)&bb[2] = *(const ulonglong2*)&sB[k][64 + tx*4];
            #pragma unroll
            for (int i = 0; i < 4; ++i)
                #pragma unroll
                for (int j = 0; j < 4; ++j)
                    acc[i][j] = fma2(a[i], bb[j], acc[i][j]);
        }
        __syncthreads();
    }
    float* out = d_part + (size_t)blockIdx.z * (RR*HH);
    #pragma unroll
    for (int i = 0; i < 4; ++i) {
        float* orow = out + (size_t)(row0 + ty*4 + i)*HH + col0;
        float2 f0 = upk(acc[i][0]), f1 = upk(acc[i][1]);
        float2 f2 = upk(acc[i][2]), f3 = upk(acc[i][3]);
        *(float4*)(orow + tx*4)      = make_float4(f0.x, f0.y, f1.x, f1.y);
        *(float4*)(orow + 64 + tx*4) = make_float4(f2.x, f2.y, f3.x, f3.y);
    }
}

// ================= reduces (vectorized, fused epilogues) =================
__global__ void __launch_bounds__(256) reduce_y(const int* __restrict__ tokens,
                                                const float* __restrict__ embed,
                                                const float* __restrict__ D) {
    int idx = blockIdx.x*256 + threadIdx.x;      // RR*HH/4 items
    int i4 = idx * 4;
    int r = i4 >> 9, h = i4 & 511;
    int tok = tokens[(r >> 4)*LL + (LL - TOUT) + (r & 15)];
    float4 u  = *(const float4*)(embed + (size_t)tok*HH + h);
    float4 dv = *(const float4*)(D + h);
    float4 s = make_float4(u.x*dv.x, u.y*dv.y, u.z*dv.z, u.w*dv.w);
    #pragma unroll
    for (int z = 0; z < SK; ++z) {
        float4 p = *(const float4*)(d_part + (size_t)z*RR*HH + i4);
        s.x += p.x; s.y += p.y; s.z += p.z; s.w += p.w;
    }
    *(float4*)(d_y + i4) = s;
}
__global__ void __launch_bounds__(256) reduce_h1(const float* __restrict__ b1) {
    int idx = blockIdx.x*256 + threadIdx.x;
    int i4 = idx * 4;
    int h = i4 & 511;
    float4 s = *(const float4*)(b1 + h);
    #pragma unroll
    for (int z = 0; z < SK; ++z) {
        float4 p = *(const float4*)(d_part + (size_t)z*RR*HH + i4);
        s.x += p.x; s.y += p.y; s.z += p.z; s.w += p.w;
    }
    s.x = fmaxf(s.x, 0.f); s.y = fmaxf(s.y, 0.f);
    s.z = fmaxf(s.z, 0.f); s.w = fmaxf(s.w, 0.f);
    *(float4*)(d_h1 + i4) = s;
}

// ================= final: out = h1 @ W2 + b2 (W2t) =================
__global__ void __launch_bounds__(256) final_out(const float* __restrict__ b2,
                                                 float* __restrict__ out) {
    int idx = blockIdx.x*256 + threadIdx.x;      // RR*VV
    int r = idx >> 5, v = idx & 31;
    const float* hrow = d_h1 + (size_t)r*HH;
    const float* wrow = d_W2t + (size_t)v*HH;
    u64 a = 0ull, b = 0ull;
    #pragma unroll 8
    for (int h = 0; h < HH; h += 4) {
        ulonglong2 hv = *(const ulonglong2*)(hrow + h);
        ulonglong2 wv = *(const ulonglong2*)(wrow + h);
        a = fma2(hv.x, wv.x, a);
        b = fma2(hv.y, wv.y, b);
    }
    float2 fa = upk(a), fb = upk(b);
    out[idx] = fa.x + fa.y + fb.x + fb.y + b2[v];
}

// ================= launcher =================
extern "C" void kernel_launch(void* const* d_in, const int* in_sizes, int n_in,
                              void* d_out, int out_size) {
    const int*   tokens  = (const int*)  d_in[0];
    const float* embed   = (const float*)d_in[1];
    const float* Lre     = (const float*)d_in[2];
    const float* Lim     = (const float*)d_in[3];
    const float* Bre     = (const float*)d_in[4];
    const float* Bim     = (const float*)d_in[5];
    const float* Cre     = (const float*)d_in[6];
    const float* Cim     = (const float*)d_in[7];
    const float* D       = (const float*)d_in[8];
    const float* logstep = (const float*)d_in[9];
    const float* W1      = (const float*)d_in[10];
    const float* b1      = (const float*)d_in[11];
    const float* W2      = (const float*)d_in[12];
    const float* b2      = (const float*)d_in[13];
    float* out = (float*)d_out;

    float *xbig_p, *cbig_p, *y_p;
    cudaGetSymbolAddress((void**)&xbig_p, d_Xbig);
    cudaGetSymbolAddress((void**)&cbig_p, d_Cbig);
    cudaGetSymbolAddress((void**)&y_p,    d_y);

    prep_all<<<PP + 16 + KXC, 256>>>(Lre, Lim, logstep, embed, Bre, Bim, W2, Cre, Cim);
    scan_chunks<<<dim3(NC, BSZ), 96>>>(tokens);
    combine_emit<<<dim3(BSZ, 2), 192>>>(tokens);
    gemm_sk<<<dim3(4, 8, SK), 256>>>(xbig_p, cbig_p, KXC);   // y partials
    reduce_y<<<(RR*HH/4)/256, 256>>>(tokens, embed, D);
    gemm_sk<<<dim3(4, 8, SK), 256>>>(y_p, W1, HH);           // h1 partials
    reduce_h1<<<(RR*HH/4)/256, 256>>>(b1);
    final_out<<<(RR*VV)/256, 256>>>(b2, out);
}